// round 4
// baseline (speedup 1.0000x reference)
#include <cuda_runtime.h>
#include <math.h>
#include <stdint.h>

#define L_  4
#define B_  8
#define H_  16
#define S_  4096
#define HD_ 64
#define D_  1024
#define Q_  4
#define V_  32000
#define SP_ (S_ + Q_)      // 4100
#define M32 (B_ * Q_)      // 32
#define SCALE_ 0.125f      // 1/sqrt(64)
#define BK_ 128            // k per tile

// ------------------------- scratch (no allocs allowed) ----------------------
__device__ float g_x[M32 * D_];
__device__ float g_qkv[M32 * 3 * D_];
__device__ float g_o[M32 * D_];
__device__ float g_h[M32 * 4 * D_];
__device__ float g_part[8 * M32 * 4096];   // split-K partials (KS<=8, N<=4096)

// ------------------------------ helpers -------------------------------------
__device__ __forceinline__ void fma2(unsigned long long& d,
                                     unsigned long long a, unsigned long long b) {
    asm("fma.rn.f32x2 %0, %1, %2, %3;" : "=l"(d) : "l"(a), "l"(b), "l"(d));
}
__device__ __forceinline__ void cp_async16(uint32_t dst, const void* src) {
    asm volatile("cp.async.cg.shared.global [%0], [%1], 16;" :: "r"(dst), "l"(src));
}
__device__ __forceinline__ void cp_commit() {
    asm volatile("cp.async.commit_group;");
}
template <int N>
__device__ __forceinline__ void cp_wait() {
    asm volatile("cp.async.wait_group %0;" :: "n"(N));
}

// ------------------------------ embedding -----------------------------------
__global__ void embed_kernel(const int* __restrict__ ids, const int* __restrict__ pos,
                             const float* __restrict__ emb, const float* __restrict__ pemb) {
    int m = blockIdx.x;
    int id = ids[m];
    int p  = pos[m];
    const float* e  = emb  + (size_t)id * D_;
    const float* pe = pemb + (size_t)p  * D_;
    for (int d = threadIdx.x; d < D_; d += blockDim.x)
        g_x[m * D_ + d] = e[d] + pe[d];
}

// ------------------------------ skinny GEMM ---------------------------------
// C[m,n] = dot(A[m,:], W[n,:]), M=32 fixed, BN=32 n per block, BK=128.
// cp.async 2-stage smem pipeline; compute uses packed fma.rn.f32x2
// (even/odd k lanes) -> half the FMA instruction count.
// kslen==K: write C with mode (0 store, 1 +res, 2 relu).
// kslen<K : grid.x = (N/32)*KS, write partials to Cout (g_part layout).
__global__ void __launch_bounds__(256, 3)
gemm32_kernel(const float* __restrict__ A, const float* __restrict__ W,
              const float* __restrict__ res, float* __restrict__ Cout,
              int N, int K, int kslen, int mode) {
    extern __shared__ float4 smem4[];
    // stage layout: [w0 1024][a0 1024][w1 1024][a1 1024] float4
    float4* w_s[2] = { smem4,        smem4 + 2048 };
    float4* a_s[2] = { smem4 + 1024, smem4 + 3072 };

    int t = threadIdx.x;
    int m = t & 31;
    int g = t >> 5;
    int nblocks = N >> 5;
    int nb = blockIdx.x % nblocks;
    int ks = blockIdx.x / nblocks;
    int k0 = ks * kslen;

    // loader mapping: rows step by 8 over i=0..3, c4 = float4 column (0..31)
    int lrow = t >> 5;                   // 0..7
    int lcol = t & 31;                   // 0..31
    const float* Wg = W + (size_t)(nb * 32 + lrow) * K + k0 + (size_t)lcol * 4;
    const float* Ag = A + (size_t)lrow * K + k0 + (size_t)lcol * 4;

    int nt = kslen / BK_;

    // ---- issue stage 0 ----
    {
        uint32_t wd = (uint32_t)__cvta_generic_to_shared(w_s[0]);
        uint32_t ad = (uint32_t)__cvta_generic_to_shared(a_s[0]);
#pragma unroll
        for (int i = 0; i < 4; i++) {
            int row = lrow + i * 8;
            cp_async16(wd + (uint32_t)(row * 32 + lcol) * 16, Wg + (size_t)(i * 8) * K);
            cp_async16(ad + (uint32_t)(lcol * 32 + (row ^ lcol)) * 16, Ag + (size_t)(i * 8) * K);
        }
        cp_commit();
    }

    unsigned long long acc[4][2];
#pragma unroll
    for (int j = 0; j < 4; j++) { acc[j][0] = 0ull; acc[j][1] = 0ull; }

    for (int it = 0; it < nt; it++) {
        if (it + 1 < nt) {
            int st = (it + 1) & 1;
            int kc = (it + 1) * BK_;
            uint32_t wd = (uint32_t)__cvta_generic_to_shared(w_s[st]);
            uint32_t ad = (uint32_t)__cvta_generic_to_shared(a_s[st]);
#pragma unroll
            for (int i = 0; i < 4; i++) {
                int row = lrow + i * 8;
                cp_async16(wd + (uint32_t)(row * 32 + lcol) * 16, Wg + (size_t)(i * 8) * K + kc);
                cp_async16(ad + (uint32_t)(lcol * 32 + (row ^ lcol)) * 16, Ag + (size_t)(i * 8) * K + kc);
            }
            cp_commit();
            cp_wait<1>();
        } else {
            cp_wait<0>();
        }
        __syncthreads();

        const float4* wr = w_s[it & 1] + g * 4 * 32;
        const float4* ar = a_s[it & 1];
#pragma unroll 4
        for (int k4 = 0; k4 < 32; k4++) {
            ulonglong2 av = *reinterpret_cast<const ulonglong2*>(&ar[k4 * 32 + (m ^ k4)]);
#pragma unroll
            for (int j = 0; j < 4; j++) {
                ulonglong2 wv = *reinterpret_cast<const ulonglong2*>(&wr[j * 32 + k4]);
                fma2(acc[j][0], av.x, wv.x);
                fma2(acc[j][1], av.y, wv.y);
            }
        }
        __syncthreads();
    }

    int n0 = nb * 32 + g * 4;
    if (kslen == K) {
#pragma unroll
        for (int j = 0; j < 4; j++) {
            float2 lo = *reinterpret_cast<float2*>(&acc[j][0]);
            float2 hi = *reinterpret_cast<float2*>(&acc[j][1]);
            float v = (lo.x + lo.y) + (hi.x + hi.y);
            int n = n0 + j;
            if (mode == 1)      v += res[(size_t)m * N + n];
            else if (mode == 2) v = fmaxf(v, 0.f);
            Cout[(size_t)m * N + n] = v;
        }
    } else {
#pragma unroll
        for (int j = 0; j < 4; j++) {
            float2 lo = *reinterpret_cast<float2*>(&acc[j][0]);
            float2 hi = *reinterpret_cast<float2*>(&acc[j][1]);
            Cout[(size_t)(ks * 32 + m) * N + n0 + j] = (lo.x + lo.y) + (hi.x + hi.y);
        }
    }
}

// split-K reduce: C = mode(sum_ks P, res)
__global__ void reduce_kernel(const float* __restrict__ P, const float* __restrict__ res,
                              float* __restrict__ C, int N, int KS, int mode) {
    int i = blockIdx.x * 256 + threadIdx.x;
    if (i >= 32 * N) return;
    float s = 0.f;
    for (int ks = 0; ks < KS; ks++) s += P[(size_t)ks * 32 * N + i];
    if (mode == 1)      s += res[i];
    else if (mode == 2) s = fmaxf(s, 0.f);
    C[i] = s;
}

// --------------------------- fused attention + KV copy ----------------------
// One block (512 thr) per (b,h). All global K/V traffic is coalesced:
// warp handles 2 rows per step; lane = (row-half sub, d-quarter dq).
// Pass 1: stream K -> scores (shfl-reduce over 16 lanes) + pres_k copy.
// Pass 2: stream V once, accumulate all 4 queries per lane + pres_v copy.
__global__ void __launch_bounds__(512, 1)
attn_kernel(const float* __restrict__ qkv,
            const float* __restrict__ pk, const float* __restrict__ pv,
            float* __restrict__ ok, float* __restrict__ ov,
            float* __restrict__ o) {
    extern __shared__ float sm[];
    float* q_sm  = sm;            // [4][64] pre-scaled
    float* kn    = sm + 256;      // new K rows [4][64]
    float* vn    = sm + 512;      // new V rows [4][64]
    float* red   = sm + 768;      // [512]
    float* inv4  = sm + 1280;     // [4] (padded)
    float* opart = sm + 1312;     // [16 warps][4 qq][64 d]
    float* scT   = sm + 5408;     // [SP][4] interleaved scores

    int t = threadIdx.x;
    int b = blockIdx.x >> 4;
    int h = blockIdx.x & 15;

    if (t < 256) {
        int qq = t >> 6, d = t & 63;
        int rowi = (b * Q_ + qq) * 3 * D_ + h * HD_ + d;
        q_sm[t] = qkv[rowi] * SCALE_;
        kn[t]   = qkv[rowi + D_];
        vn[t]   = qkv[rowi + 2 * D_];
    }
    __syncthreads();

    int w   = t >> 5;
    int l   = t & 31;
    int sub = l >> 4;
    int dq  = l & 15;

    size_t bh = (size_t)(b * H_ + h);
    const float* kb  = pk + bh * S_ * HD_;
    float*       okb = ok + bh * SP_ * HD_;

    float4 q0 = *reinterpret_cast<const float4*>(q_sm +       dq * 4);
    float4 q1 = *reinterpret_cast<const float4*>(q_sm +  64 + dq * 4);
    float4 q2 = *reinterpret_cast<const float4*>(q_sm + 128 + dq * 4);
    float4 q3 = *reinterpret_cast<const float4*>(q_sm + 192 + dq * 4);

    // ---- pass 1: K stream -> scores + pres_k ----
    for (int base = w * 4; base < 2048; base += 64) {
        float4 kv[4];
#pragma unroll
        for (int u = 0; u < 4; u++) {
            int row = (base + u) * 2 + sub;
            kv[u] = *reinterpret_cast<const float4*>(kb + (size_t)row * HD_ + dq * 4);
        }
#pragma unroll
        for (int u = 0; u < 4; u++) {
            int row = (base + u) * 2 + sub;
            *reinterpret_cast<float4*>(okb + (size_t)row * HD_ + dq * 4) = kv[u];
            float p0 = kv[u].x * q0.x + kv[u].y * q0.y + kv[u].z * q0.z + kv[u].w * q0.w;
            float p1 = kv[u].x * q1.x + kv[u].y * q1.y + kv[u].z * q1.z + kv[u].w * q1.w;
            float p2 = kv[u].x * q2.x + kv[u].y * q2.y + kv[u].z * q2.z + kv[u].w * q2.w;
            float p3 = kv[u].x * q3.x + kv[u].y * q3.y + kv[u].z * q3.z + kv[u].w * q3.w;
#pragma unroll
            for (int off = 1; off <= 8; off <<= 1) {
                p0 += __shfl_xor_sync(0xffffffffu, p0, off);
                p1 += __shfl_xor_sync(0xffffffffu, p1, off);
                p2 += __shfl_xor_sync(0xffffffffu, p2, off);
                p3 += __shfl_xor_sync(0xffffffffu, p3, off);
            }
            if (dq == 0)
                *reinterpret_cast<float4*>(scT + row * 4) = make_float4(p0, p1, p2, p3);
        }
    }
    if (w < 2) {
        int r2 = w * 2 + sub;
        float4 kv = *reinterpret_cast<const float4*>(kn + r2 * HD_ + dq * 4);
        int row = S_ + r2;
        *reinterpret_cast<float4*>(okb + (size_t)row * HD_ + dq * 4) = kv;
        float p0 = kv.x * q0.x + kv.y * q0.y + kv.z * q0.z + kv.w * q0.w;
        float p1 = kv.x * q1.x + kv.y * q1.y + kv.z * q1.z + kv.w * q1.w;
        float p2 = kv.x * q2.x + kv.y * q2.y + kv.z * q2.z + kv.w * q2.w;
        float p3 = kv.x * q3.x + kv.y * q3.y + kv.z * q3.z + kv.w * q3.w;
#pragma unroll
        for (int off = 1; off <= 8; off <<= 1) {
            p0 += __shfl_xor_sync(0xffffffffu, p0, off);
            p1 += __shfl_xor_sync(0xffffffffu, p1, off);
            p2 += __shfl_xor_sync(0xffffffffu, p2, off);
            p3 += __shfl_xor_sync(0xffffffffu, p3, off);
        }
        if (dq == 0)
            *reinterpret_cast<float4*>(scT + row * 4) = make_float4(p0, p1, p2, p3);
    }
    __syncthreads();

    // ---- softmax over scT[s][qq] ----
    {
        int qq = t & 3, sidx = t >> 2;
        float mx = -1e30f;
        for (int s = sidx; s < SP_; s += 128) mx = fmaxf(mx, scT[s * 4 + qq]);
        red[t] = mx;
        __syncthreads();
        for (int wd = 256; wd >= 4; wd >>= 1) {
            if (t < wd) red[t] = fmaxf(red[t], red[t + wd]);
            __syncthreads();
        }
        float gm = red[qq];
        __syncthreads();
        float sum = 0.f;
        for (int s = sidx; s < SP_; s += 128) {
            float e = __expf(scT[s * 4 + qq] - gm);
            scT[s * 4 + qq] = e;
            sum += e;
        }
        red[t] = sum;
        __syncthreads();
        for (int wd = 256; wd >= 4; wd >>= 1) {
            if (t < wd) red[t] += red[t + wd];
            __syncthreads();
        }
        if (t < 4) inv4[t] = 1.f / red[t];
        __syncthreads();
    }

    // ---- pass 2: V stream once -> O accumulate + pres_v ----
    const float* vb  = pv + bh * S_ * HD_;
    float*       ovb = ov + bh * SP_ * HD_;
    float4 a0 = make_float4(0.f, 0.f, 0.f, 0.f);
    float4 a1 = a0, a2 = a0, a3 = a0;

    for (int base = w * 4; base < 2048; base += 64) {
        float4 vv[4];
#pragma unroll
        for (int u = 0; u < 4; u++) {
            int row = (base + u) * 2 + sub;
            vv[u] = *reinterpret_cast<const float4*>(vb + (size_t)row * HD_ + dq * 4);
        }
#pragma unroll
        for (int u = 0; u < 4; u++) {
            int row = (base + u) * 2 + sub;
            *reinterpret_cast<float4*>(ovb + (size_t)row * HD_ + dq * 4) = vv[u];
            float4 p = *reinterpret_cast<const float4*>(scT + row * 4);
            a0.x += p.x * vv[u].x; a0.y += p.x * vv[u].y; a0.z += p.x * vv[u].z; a0.w += p.x * vv[u].w;
            a1.x += p.y * vv[u].x; a1.y += p.y * vv[u].y; a1.z += p.y * vv[u].z; a1.w += p.y * vv[u].w;
            a2.x += p.z * vv[u].x; a2.y += p.z * vv[u].y; a2.z += p.z * vv[u].z; a2.w += p.z * vv[u].w;
            a3.x += p.w * vv[u].x; a3.y += p.w * vv[u].y; a3.z += p.w * vv[u].z; a3.w += p.w * vv[u].w;
        }
    }
    if (w < 2) {
        int r2 = w * 2 + sub;
        float4 vv = *reinterpret_cast<const float4*>(vn + r2 * HD_ + dq * 4);
        int row = S_ + r2;
        *reinterpret_cast<float4*>(ovb + (size_t)row * HD_ + dq * 4) = vv;
        float4 p = *reinterpret_cast<const float4*>(scT + row * 4);
        a0.x += p.x * vv.x; a0.y += p.x * vv.y; a0.z += p.x * vv.z; a0.w += p.x * vv.w;
        a1.x += p.y * vv.x; a1.y += p.y * vv.y; a1.z += p.y * vv.z; a1.w += p.y * vv.w;
        a2.x += p.z * vv.x; a2.y += p.z * vv.y; a2.z += p.z * vv.z; a2.w += p.z * vv.w;
        a3.x += p.w * vv.x; a3.y += p.w * vv.y; a3.z += p.w * vv.z; a3.w += p.w * vv.w;
    }

    a0.x += __shfl_xor_sync(0xffffffffu, a0.x, 16); a0.y += __shfl_xor_sync(0xffffffffu, a0.y, 16);
    a0.z += __shfl_xor_sync(0xffffffffu, a0.z, 16); a0.w += __shfl_xor_sync(0xffffffffu, a0.w, 16);
    a1.x += __shfl_xor_sync(0xffffffffu, a1.x, 16); a1.y += __shfl_xor_sync(0xffffffffu, a1.y, 16);
    a1.z += __shfl_xor_sync(0xffffffffu, a1.z, 16); a1.w += __shfl_xor_sync(0xffffffffu, a1.w, 16);
    a2.x += __shfl_xor_sync(0xffffffffu, a2.x, 16); a2.y += __shfl_xor_sync(0xffffffffu, a2.y, 16);
    a2.z += __shfl_xor_sync(0xffffffffu, a2.z, 16); a2.w += __shfl_xor_sync(0xffffffffu, a2.w, 16);
    a3.x += __shfl_xor_sync(0xffffffffu, a3.x, 16); a3.y += __shfl_xor_sync(0xffffffffu, a3.y, 16);
    a3.z += __shfl_xor_sync(0xffffffffu, a3.z, 16); a3.w += __shfl_xor_sync(0xffffffffu, a3.w, 16);

    if (sub == 0) {
        *reinterpret_cast<float4*>(opart + (w * 4 + 0) * 64 + dq * 4) = a0;
        *reinterpret_cast<float4*>(opart + (w * 4 + 1) * 64 + dq * 4) = a1;
        *reinterpret_cast<float4*>(opart + (w * 4 + 2) * 64 + dq * 4) = a2;
        *reinterpret_cast<float4*>(opart + (w * 4 + 3) * 64 + dq * 4) = a3;
    }
    __syncthreads();

    if (t < 256) {
        int qq = t >> 6, d = t & 63;
        float s = 0.f;
#pragma unroll
        for (int ww = 0; ww < 16; ww++)
            s += opart[(ww * 4 + qq) * 64 + d];
        o[(b * Q_ + qq) * D_ + h * HD_ + d] = s * inv4[qq];
    }
}

// ------------------------------- launcher -----------------------------------
extern "C" void kernel_launch(void* const* d_in, const int* in_sizes, int n_in,
                              void* d_out, int out_size) {
    const int*   ids    = (const int*)d_in[0];
    const int*   pos    = (const int*)d_in[1];
    const float* past_k = (const float*)d_in[2];
    const float* past_v = (const float*)d_in[3];
    const float* emb    = (const float*)d_in[4];
    const float* pemb   = (const float*)d_in[5];
    const float* qkv_w  = (const float*)d_in[6];
    const float* out_w  = (const float*)d_in[7];
    const float* fc1_w  = (const float*)d_in[8];
    const float* fc2_w  = (const float*)d_in[9];
    const float* lm_w   = (const float*)d_in[10];

    float* out    = (float*)d_out;
    float* logits = out;
    float* pres_k = out + (size_t)M32 * V_;
    float* pres_v = pres_k + (size_t)L_ * B_ * H_ * SP_ * HD_;

    float *x, *qkvb, *ob, *hb, *part;
    cudaGetSymbolAddress((void**)&x,    g_x);
    cudaGetSymbolAddress((void**)&qkvb, g_qkv);
    cudaGetSymbolAddress((void**)&ob,   g_o);
    cudaGetSymbolAddress((void**)&hb,   g_h);
    cudaGetSymbolAddress((void**)&part, g_part);

    const int GEMM_SMEM = 4096 * 16;                      // 64 KB (2-stage W+A)
    const int ATTN_SMEM = (5408 + SP_ * 4) * 4;           // 87232 B
    cudaFuncSetAttribute(gemm32_kernel, cudaFuncAttributeMaxDynamicSharedMemorySize, GEMM_SMEM);
    cudaFuncSetAttribute(attn_kernel,   cudaFuncAttributeMaxDynamicSharedMemorySize, ATTN_SMEM);

    embed_kernel<<<M32, 256>>>(ids, pos, emb, pemb);

    for (int l = 0; l < L_; l++) {
        // qkv = x @ qkv_w^T          N=3072 K=1024, splitK 2 -> 192 blocks
        gemm32_kernel<<<96 * 2, 256, GEMM_SMEM>>>(x, qkv_w + (size_t)l * 3 * D_ * D_,
                                                  nullptr, part, 3 * D_, D_, D_ / 2, 0);
        reduce_kernel<<<(32 * 3 * D_ + 255) / 256, 256>>>(part, nullptr, qkvb, 3 * D_, 2, 0);

        attn_kernel<<<B_ * H_, 512, ATTN_SMEM>>>(
            qkvb,
            past_k + (size_t)l * B_ * H_ * S_ * HD_,
            past_v + (size_t)l * B_ * H_ * S_ * HD_,
            pres_k + (size_t)l * B_ * H_ * SP_ * HD_,
            pres_v + (size_t)l * B_ * H_ * SP_ * HD_,
            ob);

        // x += o @ out_w^T           N=1024 K=1024, splitK 8 -> 256 blocks
        gemm32_kernel<<<32 * 8, 256, GEMM_SMEM>>>(ob, out_w + (size_t)l * D_ * D_,
                                                  nullptr, part, D_, D_, D_ / 8, 0);
        reduce_kernel<<<(32 * D_) / 256, 256>>>(part, x, x, D_, 8, 1);

        // h = relu(x @ fc1_w^T)      N=4096 K=1024, splitK 2 -> 256 blocks
        gemm32_kernel<<<128 * 2, 256, GEMM_SMEM>>>(x, fc1_w + (size_t)l * 4 * D_ * D_,
                                                   nullptr, part, 4 * D_, D_, D_ / 2, 0);
        reduce_kernel<<<(32 * 4 * D_) / 256, 256>>>(part, nullptr, hb, 4 * D_, 2, 2);

        // x += h @ fc2_w^T           N=1024 K=4096, splitK 8 -> 256 blocks
        gemm32_kernel<<<32 * 8, 256, GEMM_SMEM>>>(hb, fc2_w + (size_t)l * D_ * 4 * D_,
                                                  nullptr, part, D_, 4 * D_, 4 * D_ / 8, 0);
        reduce_kernel<<<(32 * D_) / 256, 256>>>(part, x, x, D_, 8, 1);
    }

    // logits = x @ lm_head^T         N=32000 K=1024, 1000 blocks, no split
    gemm32_kernel<<<1000, 256, GEMM_SMEM>>>(x, lm_w, nullptr, logits, V_, D_, D_, 0);
}

// round 5
// speedup vs baseline: 1.2826x; 1.2826x over previous
#include <cuda_runtime.h>
#include <math.h>
#include <stdint.h>

#define L_  4
#define B_  8
#define H_  16
#define S_  4096
#define HD_ 64
#define D_  1024
#define Q_  4
#define V_  32000
#define SP_ (S_ + Q_)      // 4100
#define M32 (B_ * Q_)      // 32
#define SCALE_ 0.125f      // 1/sqrt(64)
#define BK_ 128            // k per tile

// ------------------------- scratch (no allocs allowed) ----------------------
__device__ float g_x[M32 * D_];
__device__ float g_qkv[M32 * 3 * D_];
__device__ float g_o[M32 * D_];
__device__ float g_h[M32 * 4 * D_];
__device__ float g_part[8 * M32 * 4096];   // split-K partials (KS<=8, N<=4096)

// ------------------------------ embedding -----------------------------------
__global__ void embed_kernel(const int* __restrict__ ids, const int* __restrict__ pos,
                             const float* __restrict__ emb, const float* __restrict__ pemb) {
    int m = blockIdx.x;
    int id = ids[m];
    int p  = pos[m];
    const float* e  = emb  + (size_t)id * D_;
    const float* pe = pemb + (size_t)p  * D_;
    for (int d = threadIdx.x; d < D_; d += blockDim.x)
        g_x[m * D_ + d] = e[d] + pe[d];
}

// ------------------------------ skinny GEMM ---------------------------------
// Round-3-proven structure, BK=128 for occupancy: register prefetch double
// buffer, static 32KB smem, FFMA compute, 3 CTAs/SM.
// C[m,n] = dot(A[m,:], W[n,:]), M=32, BN=32 per block.
// kslen==K: write C with mode (0 store, 1 +res, 2 relu).
// kslen<K : grid.x = (N/32)*KS, write partials to Cout (g_part layout).
__global__ void __launch_bounds__(256, 3)
gemm32_kernel(const float* __restrict__ A, const float* __restrict__ W,
              const float* __restrict__ res, float* __restrict__ Cout,
              int N, int K, int kslen, int mode) {
    __shared__ float4 w_sm[32 * 32];   // [row][col4]
    __shared__ float4 a_sm[32 * 32];   // [col4][row^col4] swizzled

    int t = threadIdx.x;
    int m = t & 31;
    int g = t >> 5;
    int nblocks = N >> 5;
    int nb = blockIdx.x % nblocks;
    int ks = blockIdx.x / nblocks;
    int k0 = ks * kslen;

    int lrow = t >> 5;          // 0..7 (+8i)
    int lcol = t & 31;          // float4 column 0..31
    const float* Wg = W + (size_t)(nb * 32 + lrow) * K + k0 + (size_t)lcol * 4;
    const float* Ag = A + (size_t)lrow * K + k0 + (size_t)lcol * 4;

    int nt = kslen >> 7;        // tiles of 128

    float4 wreg[4], areg[4];
#pragma unroll
    for (int i = 0; i < 4; i++) {
        wreg[i] = *reinterpret_cast<const float4*>(Wg + (size_t)(8 * i) * K);
        areg[i] = *reinterpret_cast<const float4*>(Ag + (size_t)(8 * i) * K);
    }

    float acc[4] = {0.f, 0.f, 0.f, 0.f};

    for (int it = 0; it < nt; it++) {
#pragma unroll
        for (int i = 0; i < 4; i++) {
            int row = lrow + 8 * i;
            w_sm[row * 32 + lcol] = wreg[i];
            a_sm[lcol * 32 + (row ^ lcol)] = areg[i];
        }
        __syncthreads();

        if (it + 1 < nt) {
            int kc = (it + 1) * BK_;
#pragma unroll
            for (int i = 0; i < 4; i++) {
                wreg[i] = *reinterpret_cast<const float4*>(Wg + (size_t)(8 * i) * K + kc);
                areg[i] = *reinterpret_cast<const float4*>(Ag + (size_t)(8 * i) * K + kc);
            }
        }

        const float4* wrow = w_sm + g * 4 * 32;
#pragma unroll 8
        for (int k4 = 0; k4 < 32; k4++) {
            float4 av = a_sm[k4 * 32 + (m ^ k4)];
            float4 w0 = wrow[k4];
            float4 w1 = wrow[32 + k4];
            float4 w2 = wrow[64 + k4];
            float4 w3 = wrow[96 + k4];
            acc[0] += av.x * w0.x + av.y * w0.y + av.z * w0.z + av.w * w0.w;
            acc[1] += av.x * w1.x + av.y * w1.y + av.z * w1.z + av.w * w1.w;
            acc[2] += av.x * w2.x + av.y * w2.y + av.z * w2.z + av.w * w2.w;
            acc[3] += av.x * w3.x + av.y * w3.y + av.z * w3.z + av.w * w3.w;
        }
        __syncthreads();
    }

    int n0 = nb * 32 + g * 4;
    if (kslen == K) {
#pragma unroll
        for (int j = 0; j < 4; j++) {
            int n = n0 + j;
            float v = acc[j];
            if (mode == 1)      v += res[(size_t)m * N + n];
            else if (mode == 2) v = fmaxf(v, 0.f);
            Cout[(size_t)m * N + n] = v;
        }
    } else {
#pragma unroll
        for (int j = 0; j < 4; j++)
            Cout[(size_t)(ks * 32 + m) * N + n0 + j] = acc[j];
    }
}

// split-K reduce: C = mode(sum_ks P, res)
__global__ void reduce_kernel(const float* __restrict__ P, const float* __restrict__ res,
                              float* __restrict__ C, int N, int KS, int mode) {
    int i = blockIdx.x * 256 + threadIdx.x;
    if (i >= 32 * N) return;
    float s = 0.f;
    for (int ks = 0; ks < KS; ks++) s += P[(size_t)ks * 32 * N + i];
    if (mode == 1)      s += res[i];
    else if (mode == 2) s = fmaxf(s, 0.f);
    C[i] = s;
}

// --------------------------- fused attention + KV copy ----------------------
// One block (512 thr) per (b,h). Batch of 8 rows per warp step (MLP=8) to
// raise in-flight bytes; otherwise identical to the proven round-3 version.
__global__ void __launch_bounds__(512, 1)
attn_kernel(const float* __restrict__ qkv,
            const float* __restrict__ pk, const float* __restrict__ pv,
            float* __restrict__ ok, float* __restrict__ ov,
            float* __restrict__ o) {
    extern __shared__ float sm[];
    float* q_sm  = sm;            // [4][64] pre-scaled
    float* kn    = sm + 256;      // new K rows [4][64]
    float* vn    = sm + 512;      // new V rows [4][64]
    float* red   = sm + 768;      // [512]
    float* inv4  = sm + 1280;     // [4] (padded)
    float* opart = sm + 1312;     // [16 warps][4 qq][64 d]
    float* scT   = sm + 5408;     // [SP][4] interleaved scores

    int t = threadIdx.x;
    int b = blockIdx.x >> 4;
    int h = blockIdx.x & 15;

    if (t < 256) {
        int qq = t >> 6, d = t & 63;
        int rowi = (b * Q_ + qq) * 3 * D_ + h * HD_ + d;
        q_sm[t] = qkv[rowi] * SCALE_;
        kn[t]   = qkv[rowi + D_];
        vn[t]   = qkv[rowi + 2 * D_];
    }
    __syncthreads();

    int w   = t >> 5;
    int l   = t & 31;
    int sub = l >> 4;
    int dq  = l & 15;

    size_t bh = (size_t)(b * H_ + h);
    const float* kb  = pk + bh * S_ * HD_;
    float*       okb = ok + bh * SP_ * HD_;

    float4 q0 = *reinterpret_cast<const float4*>(q_sm +       dq * 4);
    float4 q1 = *reinterpret_cast<const float4*>(q_sm +  64 + dq * 4);
    float4 q2 = *reinterpret_cast<const float4*>(q_sm + 128 + dq * 4);
    float4 q3 = *reinterpret_cast<const float4*>(q_sm + 192 + dq * 4);

    // ---- pass 1: K stream -> scores + pres_k ----
    for (int base = w * 8; base < 2048; base += 128) {
        float4 kv[8];
#pragma unroll
        for (int u = 0; u < 8; u++) {
            int row = (base + u) * 2 + sub;
            kv[u] = *reinterpret_cast<const float4*>(kb + (size_t)row * HD_ + dq * 4);
        }
#pragma unroll
        for (int u = 0; u < 8; u++) {
            int row = (base + u) * 2 + sub;
            *reinterpret_cast<float4*>(okb + (size_t)row * HD_ + dq * 4) = kv[u];
            float p0 = kv[u].x * q0.x + kv[u].y * q0.y + kv[u].z * q0.z + kv[u].w * q0.w;
            float p1 = kv[u].x * q1.x + kv[u].y * q1.y + kv[u].z * q1.z + kv[u].w * q1.w;
            float p2 = kv[u].x * q2.x + kv[u].y * q2.y + kv[u].z * q2.z + kv[u].w * q2.w;
            float p3 = kv[u].x * q3.x + kv[u].y * q3.y + kv[u].z * q3.z + kv[u].w * q3.w;
#pragma unroll
            for (int off = 1; off <= 8; off <<= 1) {
                p0 += __shfl_xor_sync(0xffffffffu, p0, off);
                p1 += __shfl_xor_sync(0xffffffffu, p1, off);
                p2 += __shfl_xor_sync(0xffffffffu, p2, off);
                p3 += __shfl_xor_sync(0xffffffffu, p3, off);
            }
            if (dq == 0)
                *reinterpret_cast<float4*>(scT + row * 4) = make_float4(p0, p1, p2, p3);
        }
    }
    if (w < 2) {   // new K rows (4096..4099) from smem
        int r2 = w * 2 + sub;
        float4 kv = *reinterpret_cast<const float4*>(kn + r2 * HD_ + dq * 4);
        int row = S_ + r2;
        *reinterpret_cast<float4*>(okb + (size_t)row * HD_ + dq * 4) = kv;
        float p0 = kv.x * q0.x + kv.y * q0.y + kv.z * q0.z + kv.w * q0.w;
        float p1 = kv.x * q1.x + kv.y * q1.y + kv.z * q1.z + kv.w * q1.w;
        float p2 = kv.x * q2.x + kv.y * q2.y + kv.z * q2.z + kv.w * q2.w;
        float p3 = kv.x * q3.x + kv.y * q3.y + kv.z * q3.z + kv.w * q3.w;
#pragma unroll
        for (int off = 1; off <= 8; off <<= 1) {
            p0 += __shfl_xor_sync(0xffffffffu, p0, off);
            p1 += __shfl_xor_sync(0xffffffffu, p1, off);
            p2 += __shfl_xor_sync(0xffffffffu, p2, off);
            p3 += __shfl_xor_sync(0xffffffffu, p3, off);
        }
        if (dq == 0)
            *reinterpret_cast<float4*>(scT + row * 4) = make_float4(p0, p1, p2, p3);
    }
    __syncthreads();

    // ---- softmax over scT[s][qq] ----
    {
        int qq = t & 3, sidx = t >> 2;
        float mx = -1e30f;
        for (int s = sidx; s < SP_; s += 128) mx = fmaxf(mx, scT[s * 4 + qq]);
        red[t] = mx;
        __syncthreads();
        for (int wd = 256; wd >= 4; wd >>= 1) {
            if (t < wd) red[t] = fmaxf(red[t], red[t + wd]);
            __syncthreads();
        }
        float gm = red[qq];
        __syncthreads();
        float sum = 0.f;
        for (int s = sidx; s < SP_; s += 128) {
            float e = __expf(scT[s * 4 + qq] - gm);
            scT[s * 4 + qq] = e;
            sum += e;
        }
        red[t] = sum;
        __syncthreads();
        for (int wd = 256; wd >= 4; wd >>= 1) {
            if (t < wd) red[t] += red[t + wd];
            __syncthreads();
        }
        if (t < 4) inv4[t] = 1.f / red[t];
        __syncthreads();
    }

    // ---- pass 2: V stream once -> O accumulate + pres_v ----
    const float* vb  = pv + bh * S_ * HD_;
    float*       ovb = ov + bh * SP_ * HD_;
    float4 a0 = make_float4(0.f, 0.f, 0.f, 0.f);
    float4 a1 = a0, a2 = a0, a3 = a0;

    for (int base = w * 8; base < 2048; base += 128) {
        float4 vv[8];
#pragma unroll
        for (int u = 0; u < 8; u++) {
            int row = (base + u) * 2 + sub;
            vv[u] = *reinterpret_cast<const float4*>(vb + (size_t)row * HD_ + dq * 4);
        }
#pragma unroll
        for (int u = 0; u < 8; u++) {
            int row = (base + u) * 2 + sub;
            *reinterpret_cast<float4*>(ovb + (size_t)row * HD_ + dq * 4) = vv[u];
            float4 p = *reinterpret_cast<const float4*>(scT + row * 4);
            a0.x += p.x * vv[u].x; a0.y += p.x * vv[u].y; a0.z += p.x * vv[u].z; a0.w += p.x * vv[u].w;
            a1.x += p.y * vv[u].x; a1.y += p.y * vv[u].y; a1.z += p.y * vv[u].z; a1.w += p.y * vv[u].w;
            a2.x += p.z * vv[u].x; a2.y += p.z * vv[u].y; a2.z += p.z * vv[u].z; a2.w += p.z * vv[u].w;
            a3.x += p.w * vv[u].x; a3.y += p.w * vv[u].y; a3.z += p.w * vv[u].z; a3.w += p.w * vv[u].w;
        }
    }
    if (w < 2) {
        int r2 = w * 2 + sub;
        float4 vv = *reinterpret_cast<const float4*>(vn + r2 * HD_ + dq * 4);
        int row = S_ + r2;
        *reinterpret_cast<float4*>(ovb + (size_t)row * HD_ + dq * 4) = vv;
        float4 p = *reinterpret_cast<const float4*>(scT + row * 4);
        a0.x += p.x * vv.x; a0.y += p.x * vv.y; a0.z += p.x * vv.z; a0.w += p.x * vv.w;
        a1.x += p.y * vv.x; a1.y += p.y * vv.y; a1.z += p.y * vv.z; a1.w += p.y * vv.w;
        a2.x += p.z * vv.x; a2.y += p.z * vv.y; a2.z += p.z * vv.z; a2.w += p.z * vv.w;
        a3.x += p.w * vv.x; a3.y += p.w * vv.y; a3.z += p.w * vv.z; a3.w += p.w * vv.w;
    }

    a0.x += __shfl_xor_sync(0xffffffffu, a0.x, 16); a0.y += __shfl_xor_sync(0xffffffffu, a0.y, 16);
    a0.z += __shfl_xor_sync(0xffffffffu, a0.z, 16); a0.w += __shfl_xor_sync(0xffffffffu, a0.w, 16);
    a1.x += __shfl_xor_sync(0xffffffffu, a1.x, 16); a1.y += __shfl_xor_sync(0xffffffffu, a1.y, 16);
    a1.z += __shfl_xor_sync(0xffffffffu, a1.z, 16); a1.w += __shfl_xor_sync(0xffffffffu, a1.w, 16);
    a2.x += __shfl_xor_sync(0xffffffffu, a2.x, 16); a2.y += __shfl_xor_sync(0xffffffffu, a2.y, 16);
    a2.z += __shfl_xor_sync(0xffffffffu, a2.z, 16); a2.w += __shfl_xor_sync(0xffffffffu, a2.w, 16);
    a3.x += __shfl_xor_sync(0xffffffffu, a3.x, 16); a3.y += __shfl_xor_sync(0xffffffffu, a3.y, 16);
    a3.z += __shfl_xor_sync(0xffffffffu, a3.z, 16); a3.w += __shfl_xor_sync(0xffffffffu, a3.w, 16);

    if (sub == 0) {
        *reinterpret_cast<float4*>(opart + (w * 4 + 0) * 64 + dq * 4) = a0;
        *reinterpret_cast<float4*>(opart + (w * 4 + 1) * 64 + dq * 4) = a1;
        *reinterpret_cast<float4*>(opart + (w * 4 + 2) * 64 + dq * 4) = a2;
        *reinterpret_cast<float4*>(opart + (w * 4 + 3) * 64 + dq * 4) = a3;
    }
    __syncthreads();

    if (t < 256) {
        int qq = t >> 6, d = t & 63;
        float s = 0.f;
#pragma unroll
        for (int ww = 0; ww < 16; ww++)
            s += opart[(ww * 4 + qq) * 64 + d];
        o[(b * Q_ + qq) * D_ + h * HD_ + d] = s * inv4[qq];
    }
}

// ------------------------------- launcher -----------------------------------
extern "C" void kernel_launch(void* const* d_in, const int* in_sizes, int n_in,
                              void* d_out, int out_size) {
    const int*   ids    = (const int*)d_in[0];
    const int*   pos    = (const int*)d_in[1];
    const float* past_k = (const float*)d_in[2];
    const float* past_v = (const float*)d_in[3];
    const float* emb    = (const float*)d_in[4];
    const float* pemb   = (const float*)d_in[5];
    const float* qkv_w  = (const float*)d_in[6];
    const float* out_w  = (const float*)d_in[7];
    const float* fc1_w  = (const float*)d_in[8];
    const float* fc2_w  = (const float*)d_in[9];
    const float* lm_w   = (const float*)d_in[10];

    float* out    = (float*)d_out;
    float* logits = out;
    float* pres_k = out + (size_t)M32 * V_;
    float* pres_v = pres_k + (size_t)L_ * B_ * H_ * SP_ * HD_;

    float *x, *qkvb, *ob, *hb, *part;
    cudaGetSymbolAddress((void**)&x,    g_x);
    cudaGetSymbolAddress((void**)&qkvb, g_qkv);
    cudaGetSymbolAddress((void**)&ob,   g_o);
    cudaGetSymbolAddress((void**)&hb,   g_h);
    cudaGetSymbolAddress((void**)&part, g_part);

    const int ATTN_SMEM = (5408 + SP_ * 4) * 4;           // 87232 B
    cudaFuncSetAttribute(attn_kernel, cudaFuncAttributeMaxDynamicSharedMemorySize, ATTN_SMEM);

    embed_kernel<<<M32, 256>>>(ids, pos, emb, pemb);

    for (int l = 0; l < L_; l++) {
        // qkv = x @ qkv_w^T          N=3072 K=1024, splitK4 -> 384 blocks
        gemm32_kernel<<<96 * 4, 256>>>(x, qkv_w + (size_t)l * 3 * D_ * D_,
                                       nullptr, part, 3 * D_, D_, D_ / 4, 0);
        reduce_kernel<<<(32 * 3 * D_) / 256, 256>>>(part, nullptr, qkvb, 3 * D_, 4, 0);

        attn_kernel<<<B_ * H_, 512, ATTN_SMEM>>>(
            qkvb,
            past_k + (size_t)l * B_ * H_ * S_ * HD_,
            past_v + (size_t)l * B_ * H_ * S_ * HD_,
            pres_k + (size_t)l * B_ * H_ * SP_ * HD_,
            pres_v + (size_t)l * B_ * H_ * SP_ * HD_,
            ob);

        // x += o @ out_w^T           N=1024 K=1024, splitK8 -> 256 blocks
        gemm32_kernel<<<32 * 8, 256>>>(ob, out_w + (size_t)l * D_ * D_,
                                       nullptr, part, D_, D_, D_ / 8, 0);
        reduce_kernel<<<(32 * D_) / 256, 256>>>(part, x, x, D_, 8, 1);

        // h = relu(x @ fc1_w^T)      N=4096 K=1024, splitK4 -> 512 blocks
        gemm32_kernel<<<128 * 4, 256>>>(x, fc1_w + (size_t)l * 4 * D_ * D_,
                                        nullptr, part, 4 * D_, D_, D_ / 4, 0);
        reduce_kernel<<<(32 * 4 * D_) / 256, 256>>>(part, nullptr, hb, 4 * D_, 4, 2);

        // x += h @ fc2_w^T           N=1024 K=4096, splitK8 -> 256 blocks
        gemm32_kernel<<<32 * 8, 256>>>(hb, fc2_w + (size_t)l * D_ * 4 * D_,
                                       nullptr, part, D_, 4 * D_, 4 * D_ / 8, 0);
        reduce_kernel<<<(32 * D_) / 256, 256>>>(part, x, x, D_, 8, 1);
    }

    // logits = x @ lm_head^T         N=32000 K=1024, 1000 blocks (3 CTAs/SM)
    gemm32_kernel<<<1000, 256>>>(x, lm_w, nullptr, logits, V_, D_, D_, 0);
}